// round 16
// baseline (speedup 1.0000x reference)
#include <cuda_runtime.h>
#include <cuda_fp16.h>
#include <cstdint>

// ============================================================================
// ScaledDotProductAttention  B=32, S=2048, D=128, fp32 io, int32 mask.
// Base-ISA (sm_103 target) flash attention, two kernels:
//  1) prepass: fp32 -> fp16 conversion of K, V into __device__ scratch;
//     resets the persistent tile counter. (Q converted in-consumer.)
//  2) attn: PERSISTENT CTAs (296 = 2/SM), dual balanced producer warps
//     (w4: K + mask lo, w5: V + mask hi) streaming a 2-stage K/V/MASK
//     cp.async pipeline through monolithic FULL/FREE mbarriers with
//     free-running stage cursors across tile boundaries; producer w4 grabs
//     q-tiles from a global atomic and publishes via a 2-deep smem queue.
//     4 consumer warps: mma.sync m16n8k16, single-pass fp16 scores (fp32
//     accum), no-max softmax (masked -> p = 0), O in registers, per-tile
//     epilogue. Q fragments built from fp32 gmem at tile start.
//  R16 = R15 (champion) + Q-direct (prepass -5us) + balanced dual producers.
// ============================================================================

static constexpr int B_  = 32;
static constexpr int S_  = 2048;
static constexpr int D_  = 128;
static constexpr int TQ  = 64;       // query rows per tile (16 per consumer warp)
static constexpr int BC  = 64;       // keys per iteration
static constexpr int NIT = S_ / BC;  // 32
static constexpr int NTILES = B_ * (S_ / TQ);  // 1024
static constexpr int GRID = 296;     // 2 CTAs/SM x 148 SMs

static constexpr int NELEM = B_ * S_ * D_;   // 8388608

// fp16 smem tiles: padded rows, 136 halves = 272 B stride (conflict-free ldmatrix)
static constexpr int ROWH = D_ + 8;
static constexpr int RBYT = ROWH * 2;        // 272
static constexpr int SZ_T  = BC * RBYT;      // 17408

static constexpr int OFF_KB0 = 0;
static constexpr int OFF_VB0 = OFF_KB0 + SZ_T;
static constexpr int OFF_KB1 = OFF_VB0 + SZ_T;
static constexpr int OFF_VB1 = OFF_KB1 + SZ_T;
static constexpr int OFF_MB0 = OFF_VB1 + SZ_T;
static constexpr int OFF_MB1 = OFF_MB0 + SZ_T;
static constexpr int OFF_BAR = OFF_MB1 + SZ_T;       // 104448
// FULL0 @+0, FULL1 @+8, FREE0 @+16, FREE1 @+24,
// TQF0 @+32, TQF1 @+40, TQE0 @+48, TQE1 @+56, TQID0 @+64, TQID1 @+72
static constexpr int SMEM_TOTAL = OFF_BAR + 80;      // 104528 -> 2 CTAs/SM

// fp16 scratch (device globals: allocation-free scratch)
__device__ __half g_kh[NELEM];
__device__ __half g_vh[NELEM];
__device__ unsigned int g_ctr;       // persistent tile counter (reset by prepass)

// ---------------------------------------------------------------------------
__device__ __forceinline__ uint32_t smem_u32(const void* p) {
    uint32_t a;
    asm("{ .reg .u64 t; cvta.to.shared.u64 t, %1; cvt.u32.u64 %0, t; }"
        : "=r"(a) : "l"(p));
    return a;
}

__device__ __forceinline__ void ldsm4(uint32_t* r, uint32_t a) {
    asm volatile("ldmatrix.sync.aligned.m8n8.x4.shared.b16 {%0,%1,%2,%3}, [%4];"
        : "=r"(r[0]), "=r"(r[1]), "=r"(r[2]), "=r"(r[3]) : "r"(a));
}

__device__ __forceinline__ void ldsm4t(uint32_t* r, uint32_t a) {
    asm volatile("ldmatrix.sync.aligned.m8n8.x4.trans.shared.b16 {%0,%1,%2,%3}, [%4];"
        : "=r"(r[0]), "=r"(r[1]), "=r"(r[2]), "=r"(r[3]) : "r"(a));
}

__device__ __forceinline__ void mma16816(float* c, const uint32_t* a,
                                         const uint32_t* b) {
    asm volatile(
        "mma.sync.aligned.m16n8k16.row.col.f32.f16.f16.f32 "
        "{%0,%1,%2,%3}, {%4,%5,%6,%7}, {%8,%9}, {%0,%1,%2,%3};"
        : "+f"(c[0]), "+f"(c[1]), "+f"(c[2]), "+f"(c[3])
        : "r"(a[0]), "r"(a[1]), "r"(a[2]), "r"(a[3]), "r"(b[0]), "r"(b[1]));
}

__device__ __forceinline__ void cpasync16(uint32_t dst, const void* src) {
    asm volatile("cp.async.cg.shared.global [%0], [%1], 16;"
        :: "r"(dst), "l"(src));
}

#define MBAR_INIT(addr, cnt) \
    asm volatile("mbarrier.init.shared.b64 [%0], %1;" \
        :: "r"((uint32_t)(addr)), "r"((uint32_t)(cnt)) : "memory")

#define MBAR_ARRIVE(addr) \
    asm volatile("{\n\t.reg .b64 s;\n\tmbarrier.arrive.release.cta.shared::cta.b64 s, [%0];\n\t}" \
        :: "r"((uint32_t)(addr)) : "memory")

#define CP_MBAR_ARRIVE(addr) \
    asm volatile("cp.async.mbarrier.arrive.noinc.shared.b64 [%0];" \
        :: "r"((uint32_t)(addr)) : "memory")

#define MBAR_WAIT(addr, parity) do {                                          \
    uint32_t _m = (uint32_t)(addr);                                           \
    uint32_t _p = (uint32_t)(parity);                                         \
    uint32_t _done;                                                           \
    asm volatile(                                                             \
        "{\n\t.reg .pred p;\n\t"                                              \
        "mbarrier.try_wait.parity.acquire.cta.shared::cta.b64 p, [%1], %2;\n\t" \
        "selp.b32 %0, 1, 0, p;\n\t}"                                          \
        : "=r"(_done) : "r"(_m), "r"(_p) : "memory");                         \
    if (!_done) {                                                             \
        asm volatile(                                                         \
            "{\n\t.reg .pred P1;\n\t"                                         \
            "WAIT_LOOP_%=:\n\t"                                               \
            "mbarrier.try_wait.parity.acquire.cta.shared::cta.b64 P1, [%0], %1, 0x989680;\n\t" \
            "@P1 bra.uni WAIT_DONE_%=;\n\t"                                   \
            "bra.uni WAIT_LOOP_%=;\n\t"                                       \
            "WAIT_DONE_%=:\n\t}"                                              \
            :: "r"(_m), "r"(_p) : "memory");                                  \
    }                                                                         \
} while (0)

__device__ __forceinline__ float ex2f(float x) {
    float r;
    asm("ex2.approx.ftz.f32 %0, %1;" : "=f"(r) : "f"(x));
    return r;
}

__device__ __forceinline__ uint32_t packh2(float a, float b) {
    __half2 h = __halves2half2(__float2half_rn(a), __float2half_rn(b));
    return *reinterpret_cast<uint32_t*>(&h);
}

// ---------------------------------------------------------------------------
// Pre-pass: fp32 -> fp16 scratch for K and V only. Resets tile counter.
// ---------------------------------------------------------------------------
__global__ void __launch_bounds__(256)
prepass_kernel(const float* __restrict__ Kp, const float* __restrict__ Vp) {
    if (blockIdx.x == 0 && threadIdx.x == 0) g_ctr = 0;

    const int N4 = NELEM / 4;
    uint2* kh4 = (uint2*)g_kh;
    uint2* vh4 = (uint2*)g_vh;
    for (int i = blockIdx.x * blockDim.x + threadIdx.x; i < N4;
         i += gridDim.x * blockDim.x) {
        float4 k = ((const float4*)Kp)[i];
        uint2 kk;
        kk.x = packh2(k.x, k.y);
        kk.y = packh2(k.z, k.w);
        kh4[i] = kk;

        float4 v = ((const float4*)Vp)[i];
        uint2 vv;
        vv.x = packh2(v.x, v.y);
        vv.y = packh2(v.z, v.w);
        vh4[i] = vv;
    }
}

// ---------------------------------------------------------------------------
// Main attention kernel: persistent, 192 threads = 4 consumer + 2 producer warps.
// ---------------------------------------------------------------------------
__global__ void __launch_bounds__(192, 2)
attn_kernel(const float* __restrict__ Qp, const int* __restrict__ Mk,
            float* __restrict__ Out) {
    extern __shared__ __align__(128) char smem[];
    const uint32_t sb = smem_u32(smem);
    const int tid  = threadIdx.x;
    const int lane = tid & 31;
    const int w    = tid >> 5;

    const uint32_t FULL0 = sb + OFF_BAR + 0,  FULL1 = sb + OFF_BAR + 8;
    const uint32_t FREE0 = sb + OFF_BAR + 16, FREE1 = sb + OFF_BAR + 24;
    const uint32_t TQF0  = sb + OFF_BAR + 32, TQF1  = sb + OFF_BAR + 40;
    const uint32_t TQE0  = sb + OFF_BAR + 48, TQE1  = sb + OFF_BAR + 56;
    const uint32_t TQID0 = sb + OFF_BAR + 64, TQID1 = sb + OFF_BAR + 72;

    if (tid == 0) {
        MBAR_INIT(FULL0, 64);  MBAR_INIT(FULL1, 64);   // 2 producer warps x32
        MBAR_INIT(FREE0, 128); MBAR_INIT(FREE1, 128);  // 4 consumer warps x32
        MBAR_INIT(TQF0, 1);    MBAR_INIT(TQF1, 1);
        MBAR_INIT(TQE0, 160);  MBAR_INIT(TQE1, 160);   // 4 consumers + w5
    }
    __syncthreads();

    // ======================= PRODUCER warps (w == 4, 5) ====================
    if (w >= 4) {
        const int pw = w - 4;   // 0: K + mask rows 0-31;  1: V + mask rows 32-63
        uint32_t gq = 0;
        uint32_t gi = 0;
        for (;;) {
            const int slot = gq & 1;
            int tile = 0;
            if (pw == 0) {
                // w4 publishes tile ids
                if (gq >= 2) { MBAR_WAIT(slot ? TQE1 : TQE0, ((gq - 2) >> 1) & 1); }
                if (lane == 0) {
                    tile = (int)atomicAdd(&g_ctr, 1u);
                    asm volatile("st.shared.u32 [%0], %1;"
                        :: "r"(slot ? TQID1 : TQID0), "r"((uint32_t)tile) : "memory");
                    MBAR_ARRIVE(slot ? TQF1 : TQF0);
                }
                tile = __shfl_sync(0xFFFFFFFFu, tile, 0);
            } else {
                // w5 reads tile ids like a consumer
                MBAR_WAIT(slot ? TQF1 : TQF0, (gq >> 1) & 1);
                uint32_t tu;
                asm volatile("ld.shared.u32 %0, [%1];"
                    : "=r"(tu) : "r"(slot ? TQID1 : TQID0));
                MBAR_ARRIVE(slot ? TQE1 : TQE0);
                tile = (int)tu;
            }
            gq++;
            if (tile >= NTILES) break;

            const size_t bS = (size_t)(tile >> 5) * S_;
            const int q0 = (tile & 31) * TQ;
            const int* m_base = Mk + (bS + q0) * S_;

            for (int t = 0; t < NIT; t++, gi++) {
                const int bb = gi & 1;
                if (gi >= 2) {
                    MBAR_WAIT(bb ? FREE1 : FREE0, ((gi - 2) >> 1) & 1);
                }
                const int* ms = m_base + t * BC;
                const uint32_t md = sb + (bb ? OFF_MB1 : OFF_MB0);

                if (pw == 0) {
                    const char* ks = (const char*)(g_kh + (bS + (size_t)t * BC) * D_);
                    const uint32_t kd = sb + (bb ? OFF_KB1 : OFF_KB0);
                    #pragma unroll 4
                    for (int r = 0; r < 32; r++) {
                        int i = lane + 32 * r;
                        cpasync16(kd + (i >> 4) * RBYT + (i & 15) * 16, ks + i * 16);
                    }
                    #pragma unroll 4
                    for (int r = 0; r < 16; r++) {
                        int i = lane + 32 * r;      // rows 0..31
                        int row = i >> 4, c = i & 15;
                        cpasync16(md + row * RBYT + c * 16,
                                  (const char*)(ms + (size_t)row * S_) + c * 16);
                    }
                } else {
                    const char* vs = (const char*)(g_vh + (bS + (size_t)t * BC) * D_);
                    const uint32_t vd = sb + (bb ? OFF_VB1 : OFF_VB0);
                    #pragma unroll 4
                    for (int r = 0; r < 32; r++) {
                        int i = lane + 32 * r;
                        cpasync16(vd + (i >> 4) * RBYT + (i & 15) * 16, vs + i * 16);
                    }
                    #pragma unroll 4
                    for (int r = 16; r < 32; r++) {
                        int i = lane + 32 * r;      // rows 32..63
                        int row = i >> 4, c = i & 15;
                        cpasync16(md + row * RBYT + c * 16,
                                  (const char*)(ms + (size_t)row * S_) + c * 16);
                    }
                }
                CP_MBAR_ARRIVE(bb ? FULL1 : FULL0);
            }
        }
        return;
    }

    // ======================= CONSUMER warps (w 0..3) =======================
    const int frw = w * 16 + (lane >> 2);      // fragment rows frw, frw+8
    const int fc  = (lane & 3) * 2;
    const uint32_t k_row  = (uint32_t)(((lane >> 4) & 1) * 8 + (lane & 7)) * RBYT;
    const uint32_t k_col  = (uint32_t)((lane >> 3) & 1) * 16;
    const uint32_t v_row  = (uint32_t)(((lane >> 3) & 1) * 8 + (lane & 7)) * RBYT;
    const uint32_t v_col  = (uint32_t)((lane >> 4) & 1) * 16;
    const uint32_t m_off0 = (uint32_t)frw * RBYT + (uint32_t)fc * 4;
    const uint32_t m_off1 = m_off0 + 8 * RBYT;
    const float SC = 0.08838834764831845f * 1.4426950408889634f;

    uint32_t gq = 0;
    uint32_t gi = 0;
    for (;;) {
        const int slot = gq & 1;
        MBAR_WAIT(slot ? TQF1 : TQF0, (gq >> 1) & 1);
        uint32_t tile_u;
        asm volatile("ld.shared.u32 %0, [%1];"
            : "=r"(tile_u) : "r"(slot ? TQID1 : TQID0));
        MBAR_ARRIVE(slot ? TQE1 : TQE0);
        gq++;
        const int tile = (int)tile_u;
        if (tile >= NTILES) break;

        const size_t bS = (size_t)(tile >> 5) * S_;
        const int q0 = (tile & 31) * TQ;

        // resident Q A-fragments straight from fp32 gmem, scaled + packed
        uint32_t qh[8][4];
        {
            const float* qr0 = Qp + (bS + q0 + (size_t)frw) * D_ + fc;
            const float* qr1 = qr0 + 8 * D_;
            #pragma unroll
            for (int kc = 0; kc < 8; kc++) {
                float2 a = *(const float2*)(qr0 + kc * 16);
                float2 b = *(const float2*)(qr1 + kc * 16);
                float2 c = *(const float2*)(qr0 + kc * 16 + 8);
                float2 d = *(const float2*)(qr1 + kc * 16 + 8);
                qh[kc][0] = packh2(a.x * SC, a.y * SC);
                qh[kc][1] = packh2(b.x * SC, b.y * SC);
                qh[kc][2] = packh2(c.x * SC, c.y * SC);
                qh[kc][3] = packh2(d.x * SC, d.y * SC);
            }
        }

        float O[16][4];
        #pragma unroll
        for (int i = 0; i < 16; i++)
            { O[i][0] = 0.f; O[i][1] = 0.f; O[i][2] = 0.f; O[i][3] = 0.f; }
        float sum0 = 0.f, sum1 = 0.f;

        for (int t = 0; t < NIT; t++, gi++) {
            const int bb = gi & 1;
            MBAR_WAIT(bb ? FULL1 : FULL0, (gi >> 1) & 1);

            const uint32_t kb = sb + (bb ? OFF_KB1 : OFF_KB0);
            const uint32_t vb = sb + (bb ? OFF_VB1 : OFF_VB0);
            const uint32_t mb = sb + (bb ? OFF_MB1 : OFF_MB0);

            // ---- MMA1: S = Q*K^T, single-pass fp16 (fp32 accumulate) ----
            float Sv[8][4];
            #pragma unroll
            for (int i = 0; i < 8; i++)
                { Sv[i][0] = 0.f; Sv[i][1] = 0.f; Sv[i][2] = 0.f; Sv[i][3] = 0.f; }

            #pragma unroll
            for (int kc = 0; kc < 8; kc++) {
                #pragma unroll
                for (int np = 0; np < 4; np++) {
                    uint32_t kh[4];
                    uint32_t off = (uint32_t)np * 16 * RBYT + k_row + kc * 32 + k_col;
                    ldsm4(kh, kb + off);
                    mma16816(Sv[2 * np],     qh[kc], &kh[0]);
                    mma16816(Sv[2 * np + 1], qh[kc], &kh[2]);
                }
            }

            // ---- mask (from smem) + exp2, pack P as A-fragments ----
            uint32_t P[4][4];
            #pragma unroll
            for (int j = 0; j < 8; j++) {
                int2 m0, m1;
                asm volatile("ld.shared.v2.u32 {%0,%1}, [%2];"
                    : "=r"(m0.x), "=r"(m0.y) : "r"(mb + m_off0 + j * 32));
                asm volatile("ld.shared.v2.u32 {%0,%1}, [%2];"
                    : "=r"(m1.x), "=r"(m1.y) : "r"(mb + m_off1 + j * 32));
                float p0 = m0.x ? ex2f(Sv[j][0]) : 0.f;
                float p1 = m0.y ? ex2f(Sv[j][1]) : 0.f;
                float p2 = m1.x ? ex2f(Sv[j][2]) : 0.f;
                float p3 = m1.y ? ex2f(Sv[j][3]) : 0.f;
                sum0 += p0 + p1;
                sum1 += p2 + p3;
                P[j >> 1][(j & 1) * 2 + 0] = packh2(p0, p1);
                P[j >> 1][(j & 1) * 2 + 1] = packh2(p2, p3);
            }

            // ---- MMA2: O += P * V  (V B-frags via ldmatrix.trans) ----
            #pragma unroll
            for (int kk = 0; kk < 4; kk++) {
                #pragma unroll
                for (int nd = 0; nd < 8; nd++) {
                    uint32_t vbr[4];
                    uint32_t off = (uint32_t)kk * 16 * RBYT + v_row + nd * 32 + v_col;
                    ldsm4t(vbr, vb + off);
                    mma16816(O[2 * nd],     P[kk], &vbr[0]);
                    mma16816(O[2 * nd + 1], P[kk], &vbr[2]);
                }
            }

            MBAR_ARRIVE(bb ? FREE1 : FREE0);   // buffer free for producers
        }

        // ---- rowsum reduce + normalize + write O for this tile ----
        sum0 += __shfl_xor_sync(0xFFFFFFFFu, sum0, 1);
        sum0 += __shfl_xor_sync(0xFFFFFFFFu, sum0, 2);
        sum1 += __shfl_xor_sync(0xFFFFFFFFu, sum1, 1);
        sum1 += __shfl_xor_sync(0xFFFFFFFFu, sum1, 2);
        const float inv0 = 1.0f / sum0;
        const float inv1 = 1.0f / sum1;

        float* o0 = Out + (bS + q0 + frw) * D_ + fc;
        float* o1 = o0 + 8 * D_;
        #pragma unroll
        for (int nd = 0; nd < 16; nd++) {
            float2 a, c;
            a.x = O[nd][0] * inv0; a.y = O[nd][1] * inv0;
            c.x = O[nd][2] * inv1; c.y = O[nd][3] * inv1;
            *(float2*)(o0 + nd * 8) = a;
            *(float2*)(o1 + nd * 8) = c;
        }
    }
}

// ---------------------------------------------------------------------------
extern "C" void kernel_launch(void* const* d_in, const int* in_sizes, int n_in,
                              void* d_out, int out_size) {
    const float* Q = (const float*)d_in[0];
    const float* K = (const float*)d_in[1];
    const float* V = (const float*)d_in[2];
    const int* mask = (const int*)d_in[3];
    float* out = (float*)d_out;

    prepass_kernel<<<2048, 256>>>(K, V);

    cudaFuncSetAttribute(attn_kernel,
                         cudaFuncAttributeMaxDynamicSharedMemorySize, SMEM_TOTAL);
    attn_kernel<<<GRID, 192, SMEM_TOTAL>>>(Q, mask, out);
}

// round 17
// speedup vs baseline: 1.0817x; 1.0817x over previous
#include <cuda_runtime.h>
#include <cuda_fp16.h>
#include <cstdint>

// ============================================================================
// ScaledDotProductAttention  B=32, S=2048, D=128, fp32 io, int32 mask.
// Base-ISA (sm_103 target) flash attention, two kernels:
//  1) prepass: fp32 -> fp16 conversion of K, V into __device__ scratch;
//     resets the persistent tile counter. (Q converted in-consumer.)
//  2) attn: PERSISTENT CTAs (296 = 2/SM), single producer warp streaming the
//     2-stage K/V/MASK cp.async pipeline (monolithic FULL/FREE mbarriers,
//     free-running stage cursor across tile boundaries); producer grabs
//     q-tiles from a global atomic and publishes via a 2-deep smem queue.
//     4 consumer warps: mma.sync m16n8k16, single-pass fp16 scores (fp32
//     accum), no-max softmax (masked -> p = 0), O in registers, per-tile
//     epilogue; Q fragments built from fp32 gmem at tile start.
//  R17 = R15 (champion, 225us) + Q-direct only (dual-producer of R16 reverted).
// ============================================================================

static constexpr int B_  = 32;
static constexpr int S_  = 2048;
static constexpr int D_  = 128;
static constexpr int TQ  = 64;       // query rows per tile (16 per consumer warp)
static constexpr int BC  = 64;       // keys per iteration
static constexpr int NIT = S_ / BC;  // 32
static constexpr int NTILES = B_ * (S_ / TQ);  // 1024
static constexpr int GRID = 296;     // 2 CTAs/SM x 148 SMs

static constexpr int NELEM = B_ * S_ * D_;   // 8388608

// fp16 smem tiles: padded rows, 136 halves = 272 B stride (conflict-free ldmatrix)
static constexpr int ROWH = D_ + 8;
static constexpr int RBYT = ROWH * 2;        // 272
static constexpr int SZ_T  = BC * RBYT;      // 17408

static constexpr int OFF_KB0 = 0;
static constexpr int OFF_VB0 = OFF_KB0 + SZ_T;
static constexpr int OFF_KB1 = OFF_VB0 + SZ_T;
static constexpr int OFF_VB1 = OFF_KB1 + SZ_T;
static constexpr int OFF_MB0 = OFF_VB1 + SZ_T;
static constexpr int OFF_MB1 = OFF_MB0 + SZ_T;
static constexpr int OFF_BAR = OFF_MB1 + SZ_T;       // 104448
// FULL0 @+0, FULL1 @+8, FREE0 @+16, FREE1 @+24,
// TQF0 @+32, TQF1 @+40, TQE0 @+48, TQE1 @+56, TQID0 @+64, TQID1 @+72
static constexpr int SMEM_TOTAL = OFF_BAR + 80;      // 104528 -> 2 CTAs/SM

// fp16 scratch (device globals: allocation-free scratch)
__device__ __half g_kh[NELEM];
__device__ __half g_vh[NELEM];
__device__ unsigned int g_ctr;       // persistent tile counter (reset by prepass)

// ---------------------------------------------------------------------------
__device__ __forceinline__ uint32_t smem_u32(const void* p) {
    uint32_t a;
    asm("{ .reg .u64 t; cvta.to.shared.u64 t, %1; cvt.u32.u64 %0, t; }"
        : "=r"(a) : "l"(p));
    return a;
}

__device__ __forceinline__ void ldsm4(uint32_t* r, uint32_t a) {
    asm volatile("ldmatrix.sync.aligned.m8n8.x4.shared.b16 {%0,%1,%2,%3}, [%4];"
        : "=r"(r[0]), "=r"(r[1]), "=r"(r[2]), "=r"(r[3]) : "r"(a));
}

__device__ __forceinline__ void ldsm4t(uint32_t* r, uint32_t a) {
    asm volatile("ldmatrix.sync.aligned.m8n8.x4.trans.shared.b16 {%0,%1,%2,%3}, [%4];"
        : "=r"(r[0]), "=r"(r[1]), "=r"(r[2]), "=r"(r[3]) : "r"(a));
}

__device__ __forceinline__ void mma16816(float* c, const uint32_t* a,
                                         const uint32_t* b) {
    asm volatile(
        "mma.sync.aligned.m16n8k16.row.col.f32.f16.f16.f32 "
        "{%0,%1,%2,%3}, {%4,%5,%6,%7}, {%8,%9}, {%0,%1,%2,%3};"
        : "+f"(c[0]), "+f"(c[1]), "+f"(c[2]), "+f"(c[3])
        : "r"(a[0]), "r"(a[1]), "r"(a[2]), "r"(a[3]), "r"(b[0]), "r"(b[1]));
}

__device__ __forceinline__ void cpasync16(uint32_t dst, const void* src) {
    asm volatile("cp.async.cg.shared.global [%0], [%1], 16;"
        :: "r"(dst), "l"(src));
}

#define MBAR_INIT(addr, cnt) \
    asm volatile("mbarrier.init.shared.b64 [%0], %1;" \
        :: "r"((uint32_t)(addr)), "r"((uint32_t)(cnt)) : "memory")

#define MBAR_ARRIVE(addr) \
    asm volatile("{\n\t.reg .b64 s;\n\tmbarrier.arrive.release.cta.shared::cta.b64 s, [%0];\n\t}" \
        :: "r"((uint32_t)(addr)) : "memory")

#define CP_MBAR_ARRIVE(addr) \
    asm volatile("cp.async.mbarrier.arrive.noinc.shared.b64 [%0];" \
        :: "r"((uint32_t)(addr)) : "memory")

#define MBAR_WAIT(addr, parity) do {                                          \
    uint32_t _m = (uint32_t)(addr);                                           \
    uint32_t _p = (uint32_t)(parity);                                         \
    uint32_t _done;                                                           \
    asm volatile(                                                             \
        "{\n\t.reg .pred p;\n\t"                                              \
        "mbarrier.try_wait.parity.acquire.cta.shared::cta.b64 p, [%1], %2;\n\t" \
        "selp.b32 %0, 1, 0, p;\n\t}"                                          \
        : "=r"(_done) : "r"(_m), "r"(_p) : "memory");                         \
    if (!_done) {                                                             \
        asm volatile(                                                         \
            "{\n\t.reg .pred P1;\n\t"                                         \
            "WAIT_LOOP_%=:\n\t"                                               \
            "mbarrier.try_wait.parity.acquire.cta.shared::cta.b64 P1, [%0], %1, 0x989680;\n\t" \
            "@P1 bra.uni WAIT_DONE_%=;\n\t"                                   \
            "bra.uni WAIT_LOOP_%=;\n\t"                                       \
            "WAIT_DONE_%=:\n\t}"                                              \
            :: "r"(_m), "r"(_p) : "memory");                                  \
    }                                                                         \
} while (0)

__device__ __forceinline__ float ex2f(float x) {
    float r;
    asm("ex2.approx.ftz.f32 %0, %1;" : "=f"(r) : "f"(x));
    return r;
}

__device__ __forceinline__ uint32_t packh2(float a, float b) {
    __half2 h = __halves2half2(__float2half_rn(a), __float2half_rn(b));
    return *reinterpret_cast<uint32_t*>(&h);
}

// ---------------------------------------------------------------------------
// Pre-pass: fp32 -> fp16 scratch for K and V only. Resets tile counter.
// ---------------------------------------------------------------------------
__global__ void __launch_bounds__(256)
prepass_kernel(const float* __restrict__ Kp, const float* __restrict__ Vp) {
    if (blockIdx.x == 0 && threadIdx.x == 0) g_ctr = 0;

    const int N4 = NELEM / 4;
    uint2* kh4 = (uint2*)g_kh;
    uint2* vh4 = (uint2*)g_vh;
    for (int i = blockIdx.x * blockDim.x + threadIdx.x; i < N4;
         i += gridDim.x * blockDim.x) {
        float4 k = ((const float4*)Kp)[i];
        uint2 kk;
        kk.x = packh2(k.x, k.y);
        kk.y = packh2(k.z, k.w);
        kh4[i] = kk;

        float4 v = ((const float4*)Vp)[i];
        uint2 vv;
        vv.x = packh2(v.x, v.y);
        vv.y = packh2(v.z, v.w);
        vh4[i] = vv;
    }
}

// ---------------------------------------------------------------------------
// Main attention kernel: persistent, 160 threads = 4 consumer + 1 producer warp.
// ---------------------------------------------------------------------------
__global__ void __launch_bounds__(160, 2)
attn_kernel(const float* __restrict__ Qp, const int* __restrict__ Mk,
            float* __restrict__ Out) {
    extern __shared__ __align__(128) char smem[];
    const uint32_t sb = smem_u32(smem);
    const int tid  = threadIdx.x;
    const int lane = tid & 31;
    const int w    = tid >> 5;

    const uint32_t FULL0 = sb + OFF_BAR + 0,  FULL1 = sb + OFF_BAR + 8;
    const uint32_t FREE0 = sb + OFF_BAR + 16, FREE1 = sb + OFF_BAR + 24;
    const uint32_t TQF0  = sb + OFF_BAR + 32, TQF1  = sb + OFF_BAR + 40;
    const uint32_t TQE0  = sb + OFF_BAR + 48, TQE1  = sb + OFF_BAR + 56;
    const uint32_t TQID0 = sb + OFF_BAR + 64, TQID1 = sb + OFF_BAR + 72;

    if (tid == 0) {
        MBAR_INIT(FULL0, 32);  MBAR_INIT(FULL1, 32);
        MBAR_INIT(FREE0, 128); MBAR_INIT(FREE1, 128);
        MBAR_INIT(TQF0, 1);    MBAR_INIT(TQF1, 1);
        MBAR_INIT(TQE0, 128);  MBAR_INIT(TQE1, 128);
    }
    __syncthreads();

    // ======================= PRODUCER warp (w == 4) =======================
    if (w == 4) {
        uint32_t gq = 0;    // tiles grabbed/published
        uint32_t gi = 0;    // global fill-iteration counter (stage cursor)
        for (;;) {
            const int slot = gq & 1;
            if (gq >= 2) { MBAR_WAIT(slot ? TQE1 : TQE0, ((gq - 2) >> 1) & 1); }
            int tile = 0;
            if (lane == 0) {
                tile = (int)atomicAdd(&g_ctr, 1u);
                asm volatile("st.shared.u32 [%0], %1;"
                    :: "r"(slot ? TQID1 : TQID0), "r"((uint32_t)tile) : "memory");
                MBAR_ARRIVE(slot ? TQF1 : TQF0);
            }
            tile = __shfl_sync(0xFFFFFFFFu, tile, 0);
            gq++;
            if (tile >= NTILES) break;

            const size_t bS = (size_t)(tile >> 5) * S_;
            const int q0 = (tile & 31) * TQ;
            const int* m_base = Mk + (bS + q0) * S_;

            for (int t = 0; t < NIT; t++, gi++) {
                const int bb = gi & 1;
                if (gi >= 2) {
                    MBAR_WAIT(bb ? FREE1 : FREE0, ((gi - 2) >> 1) & 1);
                }
                const char* ks = (const char*)(g_kh + (bS + (size_t)t * BC) * D_);
                const char* vs = (const char*)(g_vh + (bS + (size_t)t * BC) * D_);
                const int*  ms = m_base + t * BC;
                const uint32_t kd = sb + (bb ? OFF_KB1 : OFF_KB0);
                const uint32_t vd = sb + (bb ? OFF_VB1 : OFF_VB0);
                const uint32_t md = sb + (bb ? OFF_MB1 : OFF_MB0);
                #pragma unroll 4
                for (int r = 0; r < 32; r++) {
                    int i = lane + 32 * r;
                    int row = i >> 4;
                    int c   = i & 15;
                    uint32_t so = row * RBYT + c * 16;
                    cpasync16(kd + so, ks + i * 16);
                    cpasync16(vd + so, vs + i * 16);
                    cpasync16(md + so,
                              (const char*)(ms + (size_t)row * S_) + c * 16);
                }
                CP_MBAR_ARRIVE(bb ? FULL1 : FULL0);
            }
        }
        return;
    }

    // ======================= CONSUMER warps (w 0..3) =======================
    const int frw = w * 16 + (lane >> 2);      // fragment rows frw, frw+8
    const int fc  = (lane & 3) * 2;
    const uint32_t k_row  = (uint32_t)(((lane >> 4) & 1) * 8 + (lane & 7)) * RBYT;
    const uint32_t k_col  = (uint32_t)((lane >> 3) & 1) * 16;
    const uint32_t v_row  = (uint32_t)(((lane >> 3) & 1) * 8 + (lane & 7)) * RBYT;
    const uint32_t v_col  = (uint32_t)((lane >> 4) & 1) * 16;
    const uint32_t m_off0 = (uint32_t)frw * RBYT + (uint32_t)fc * 4;
    const uint32_t m_off1 = m_off0 + 8 * RBYT;
    const float SC = 0.08838834764831845f * 1.4426950408889634f;

    uint32_t gq = 0;    // tiles consumed
    uint32_t gi = 0;    // global consume-iteration counter (stage cursor)
    for (;;) {
        const int slot = gq & 1;
        MBAR_WAIT(slot ? TQF1 : TQF0, (gq >> 1) & 1);
        uint32_t tile_u;
        asm volatile("ld.shared.u32 %0, [%1];"
            : "=r"(tile_u) : "r"(slot ? TQID1 : TQID0));
        MBAR_ARRIVE(slot ? TQE1 : TQE0);
        gq++;
        const int tile = (int)tile_u;
        if (tile >= NTILES) break;

        const size_t bS = (size_t)(tile >> 5) * S_;
        const int q0 = (tile & 31) * TQ;

        // resident Q A-fragments straight from fp32 gmem, scaled + packed
        // (identical rounding to the old prepass path -> same rel_err)
        uint32_t qh[8][4];
        {
            const float* qr0 = Qp + (bS + q0 + (size_t)frw) * D_ + fc;
            const float* qr1 = qr0 + 8 * D_;
            #pragma unroll
            for (int kc = 0; kc < 8; kc++) {
                float2 a = *(const float2*)(qr0 + kc * 16);
                float2 b = *(const float2*)(qr1 + kc * 16);
                float2 c = *(const float2*)(qr0 + kc * 16 + 8);
                float2 d = *(const float2*)(qr1 + kc * 16 + 8);
                qh[kc][0] = packh2(a.x * SC, a.y * SC);
                qh[kc][1] = packh2(b.x * SC, b.y * SC);
                qh[kc][2] = packh2(c.x * SC, c.y * SC);
                qh[kc][3] = packh2(d.x * SC, d.y * SC);
            }
        }

        float O[16][4];
        #pragma unroll
        for (int i = 0; i < 16; i++)
            { O[i][0] = 0.f; O[i][1] = 0.f; O[i][2] = 0.f; O[i][3] = 0.f; }
        float sum0 = 0.f, sum1 = 0.f;

        for (int t = 0; t < NIT; t++, gi++) {
            const int bb = gi & 1;
            MBAR_WAIT(bb ? FULL1 : FULL0, (gi >> 1) & 1);

            const uint32_t kb = sb + (bb ? OFF_KB1 : OFF_KB0);
            const uint32_t vb = sb + (bb ? OFF_VB1 : OFF_VB0);
            const uint32_t mb = sb + (bb ? OFF_MB1 : OFF_MB0);

            // ---- MMA1: S = Q*K^T, single-pass fp16 (fp32 accumulate) ----
            float Sv[8][4];
            #pragma unroll
            for (int i = 0; i < 8; i++)
                { Sv[i][0] = 0.f; Sv[i][1] = 0.f; Sv[i][2] = 0.f; Sv[i][3] = 0.f; }

            #pragma unroll
            for (int kc = 0; kc < 8; kc++) {
                #pragma unroll
                for (int np = 0; np < 4; np++) {
                    uint32_t kh[4];
                    uint32_t off = (uint32_t)np * 16 * RBYT + k_row + kc * 32 + k_col;
                    ldsm4(kh, kb + off);
                    mma16816(Sv[2 * np],     qh[kc], &kh[0]);
                    mma16816(Sv[2 * np + 1], qh[kc], &kh[2]);
                }
            }

            // ---- mask (from smem) + exp2, pack P as A-fragments ----
            uint32_t P[4][4];
            #pragma unroll
            for (int j = 0; j < 8; j++) {
                int2 m0, m1;
                asm volatile("ld.shared.v2.u32 {%0,%1}, [%2];"
                    : "=r"(m0.x), "=r"(m0.y) : "r"(mb + m_off0 + j * 32));
                asm volatile("ld.shared.v2.u32 {%0,%1}, [%2];"
                    : "=r"(m1.x), "=r"(m1.y) : "r"(mb + m_off1 + j * 32));
                float p0 = m0.x ? ex2f(Sv[j][0]) : 0.f;
                float p1 = m0.y ? ex2f(Sv[j][1]) : 0.f;
                float p2 = m1.x ? ex2f(Sv[j][2]) : 0.f;
                float p3 = m1.y ? ex2f(Sv[j][3]) : 0.f;
                sum0 += p0 + p1;
                sum1 += p2 + p3;
                P[j >> 1][(j & 1) * 2 + 0] = packh2(p0, p1);
                P[j >> 1][(j & 1) * 2 + 1] = packh2(p2, p3);
            }

            // ---- MMA2: O += P * V  (V B-frags via ldmatrix.trans) ----
            #pragma unroll
            for (int kk = 0; kk < 4; kk++) {
                #pragma unroll
                for (int nd = 0; nd < 8; nd++) {
                    uint32_t vbr[4];
                    uint32_t off = (uint32_t)kk * 16 * RBYT + v_row + nd * 32 + v_col;
                    ldsm4t(vbr, vb + off);
                    mma16816(O[2 * nd],     P[kk], &vbr[0]);
                    mma16816(O[2 * nd + 1], P[kk], &vbr[2]);
                }
            }

            MBAR_ARRIVE(bb ? FREE1 : FREE0);   // buffer free for producer
        }

        // ---- rowsum reduce + normalize + write O for this tile ----
        sum0 += __shfl_xor_sync(0xFFFFFFFFu, sum0, 1);
        sum0 += __shfl_xor_sync(0xFFFFFFFFu, sum0, 2);
        sum1 += __shfl_xor_sync(0xFFFFFFFFu, sum1, 1);
        sum1 += __shfl_xor_sync(0xFFFFFFFFu, sum1, 2);
        const float inv0 = 1.0f / sum0;
        const float inv1 = 1.0f / sum1;

        float* o0 = Out + (bS + q0 + frw) * D_ + fc;
        float* o1 = o0 + 8 * D_;
        #pragma unroll
        for (int nd = 0; nd < 16; nd++) {
            float2 a, c;
            a.x = O[nd][0] * inv0; a.y = O[nd][1] * inv0;
            c.x = O[nd][2] * inv1; c.y = O[nd][3] * inv1;
            *(float2*)(o0 + nd * 8) = a;
            *(float2*)(o1 + nd * 8) = c;
        }
    }
}

// ---------------------------------------------------------------------------
extern "C" void kernel_launch(void* const* d_in, const int* in_sizes, int n_in,
                              void* d_out, int out_size) {
    const float* Q = (const float*)d_in[0];
    const float* K = (const float*)d_in[1];
    const float* V = (const float*)d_in[2];
    const int* mask = (const int*)d_in[3];
    float* out = (float*)d_out;

    prepass_kernel<<<2048, 256>>>(K, V);

    cudaFuncSetAttribute(attn_kernel,
                         cudaFuncAttributeMaxDynamicSharedMemorySize, SMEM_TOTAL);
    attn_kernel<<<GRID, 160, SMEM_TOTAL>>>(Q, mask, out);
}